// round 13
// baseline (speedup 1.0000x reference)
#include <cuda_runtime.h>
#include <cuda_bf16.h>
#include <cuda_pipeline.h>
#include <mma.h>
#include <math.h>

using namespace nvcuda;

__device__ int g_ps[2048];
__device__ int g_cnt[10000];
__device__ int g_hit[320000];
__device__ __nv_bfloat16 g_Ah[524288];
__device__ __nv_bfloat16 g_Al[524288];
__device__ __nv_bfloat16 g_Ph[1294336];
__device__ __nv_bfloat16 g_Pl[1294336];

__global__ void __launch_bounds__(256) k1(const float* oq, const float* ok,
    const float* pY, const float* q, float* out)
{
  int row = blockIdx.x, t = threadIdx.x;
  const float4* a4 = (const float4*)(oq + (size_t)row * 10000);
  const float4* b4 = (const float4*)(ok + (size_t)row * 10000);
  const float4* y4 = (const float4*)(pY + (size_t)row * 10000);
  float bq = -INFINITY, bk = -INFINITY;
  int iq = 0, ik = 0;
  for (int i = t; i < 2500; i += 256) {
    float4 y = y4[i], a = a4[i], b = b4[i];
    float w0 = y.x != 0.f ? 1.f : 0.1f;
    float w1 = y.y != 0.f ? 1.f : 0.1f;
    float w2 = y.z != 0.f ? 1.f : 0.1f;
    float w3 = y.w != 0.f ? 1.f : 0.1f;
    float va0 = a.x * w0, va1 = a.y * w1, va2 = a.z * w2, va3 = a.w * w3;
    float vb0 = b.x * w0, vb1 = b.y * w1, vb2 = b.z * w2, vb3 = b.w * w3;
    if (va0 > bq) { bq = va0; iq = i * 4; }
    if (va1 > bq) { bq = va1; iq = i * 4 + 1; }
    if (va2 > bq) { bq = va2; iq = i * 4 + 2; }
    if (va3 > bq) { bq = va3; iq = i * 4 + 3; }
    if (vb0 > bk) { bk = vb0; ik = i * 4; }
    if (vb1 > bk) { bk = vb1; ik = i * 4 + 1; }
    if (vb2 > bk) { bk = vb2; ik = i * 4 + 2; }
    if (vb3 > bk) { bk = vb3; ik = i * 4 + 3; }
  }
  if (t < 32) {
    const float4* q4 = (const float4*)(q + (size_t)row * 128);
    float4* oc = (float4*)(out + 61440000ull + (size_t)row * 128);
    oc[t] = q4[t];
  }
  __shared__ float sv[256];
  __shared__ int si[256];
  sv[t] = bq; si[t] = iq;
  __syncthreads();
  for (int s = 128; s > 0; s >>= 1) {
    if (t < s) {
      float v = sv[t + s]; int j = si[t + s];
      if (v > sv[t] || (v == sv[t] && j < si[t])) { sv[t] = v; si[t] = j; }
    }
    __syncthreads();
  }
  if (t == 0) g_ps[row] = si[0];
  __syncthreads();
  sv[t] = bk; si[t] = ik;
  __syncthreads();
  for (int s = 128; s > 0; s >>= 1) {
    if (t < s) {
      float v = sv[t + s]; int j = si[t + s];
      if (v > sv[t] || (v == sv[t] && j < si[t])) { sv[t] = v; si[t] = j; }
    }
    __syncthreads();
  }
  if (t == 0) g_ps[1024 + row] = si[0];
}

__device__ __forceinline__ void sp4(float4 v, __nv_bfloat162* dh, __nv_bfloat162* dl)
{
  __nv_bfloat16 h0 = __float2bfloat16_rn(v.x), h1 = __float2bfloat16_rn(v.y);
  __nv_bfloat16 h2 = __float2bfloat16_rn(v.z), h3 = __float2bfloat16_rn(v.w);
  __nv_bfloat16 l0 = __float2bfloat16_rn(v.x - __bfloat162float(h0));
  __nv_bfloat16 l1 = __float2bfloat16_rn(v.y - __bfloat162float(h1));
  __nv_bfloat16 l2 = __float2bfloat16_rn(v.z - __bfloat162float(h2));
  __nv_bfloat16 l3 = __float2bfloat16_rn(v.w - __bfloat162float(h3));
  dh[0] = __halves2bfloat162(h0, h1);
  dh[1] = __halves2bfloat162(h2, h3);
  dl[0] = __halves2bfloat162(l0, l1);
  dl[1] = __halves2bfloat162(l2, l3);
}

__global__ void __launch_bounds__(256) k2(const float* q, const float* k,
    const float* qm, const float* km, const float* P)
{
  int i = blockIdx.x * 256 + threadIdx.x;
  if (i < 10000) g_cnt[i] = 0;
  if (i < 131072) {
    int s = i >> 15;
    const float4* sp = s == 0 ? (const float4*)q : s == 1 ? (const float4*)k :
                       s == 2 ? (const float4*)qm : (const float4*)km;
    sp4(sp[i & 32767], (__nv_bfloat162*)g_Ah + (size_t)i * 2,
        (__nv_bfloat162*)g_Al + (size_t)i * 2);
  } else if (i < 451072) {
    int e = i - 131072;
    sp4(((const float4*)P)[e], (__nv_bfloat162*)g_Ph + (size_t)e * 2,
        (__nv_bfloat162*)g_Pl + (size_t)e * 2);
  } else if (i < 454656) {
    int e = i - 131072;
    sp4(make_float4(0.f, 0.f, 0.f, 0.f), (__nv_bfloat162*)g_Ph + (size_t)e * 2,
        (__nv_bfloat162*)g_Pl + (size_t)e * 2);
  }
}

__global__ void __launch_bounds__(256) k3(float* out, const float* oq,
    const float* ok, float* outbase)
{
  extern __shared__ __nv_bfloat16 sm[];
  int t = threadIdx.x;
  int bn = blockIdx.x * 128, bm = blockIdx.y * 128;
  int wid = t >> 5;
  int wm = (wid >> 2) * 64;
  int wn = (wid & 3) * 32;

  const __nv_bfloat16* gA0 = g_Ah + (size_t)bm * 128;
  const __nv_bfloat16* gA1 = g_Al + (size_t)bm * 128;
  const __nv_bfloat16* gB0 = g_Ph + (size_t)bn * 128;
  const __nv_bfloat16* gB1 = g_Pl + (size_t)bn * 128;

  for (int st = 0; st < 2; st++) {
    int kc = st * 32;
    for (int i = t; i < 2048; i += 256) {
      int a = i >> 9, idx = i & 511;
      int r = idx >> 2, c = (idx & 3) * 8;
      const __nv_bfloat16* src =
          (a == 0 ? gA0 : a == 1 ? gA1 : a == 2 ? gB0 : gB1)
          + (size_t)r * 128 + kc + c;
      __pipeline_memcpy_async(sm + st * 20480 + a * 5120 + r * 40 + c, src, 16);
    }
    __pipeline_commit();
  }

  // fused pass-through copy of output_q / output_k (fills the pipeline wait)
  {
    size_t cb = (size_t)(blockIdx.y * 79 + blockIdx.x) * 2026;
    size_t ce = cb + 2026;
    if (ce > 5120000ull) ce = 5120000ull;
    const float4* sq = (const float4*)oq;
    const float4* sk = (const float4*)ok;
    float4* dst = (float4*)outbase;
    for (size_t j = cb + t; j < ce; j += 256)
      dst[j] = j < 2560000ull ? sq[j] : sk[j - 2560000ull];
  }

  wmma::fragment<wmma::accumulator, 16, 16, 16, float> acc[4][2];
  for (int i = 0; i < 4; i++)
    for (int j = 0; j < 2; j++)
      wmma::fill_fragment(acc[i][j], 0.0f);

  for (int kc = 0; kc < 4; kc++) {
    if (kc >= 2) __pipeline_wait_prior(0);
    else __pipeline_wait_prior(1);
    __syncthreads();
    __nv_bfloat16* sAh = sm + (kc & 1) * 20480;
    __nv_bfloat16* sAl = sAh + 5120;
    __nv_bfloat16* sBh = sAh + 10240;
    __nv_bfloat16* sBl = sAh + 15360;
    for (int kk = 0; kk < 32; kk += 16) {
      wmma::fragment<wmma::matrix_b, 16, 16, 16, __nv_bfloat16, wmma::col_major> bh[2], bl[2];
      for (int j = 0; j < 2; j++) {
        wmma::load_matrix_sync(bh[j], sBh + (wn + j * 16) * 40 + kk, 40);
        wmma::load_matrix_sync(bl[j], sBl + (wn + j * 16) * 40 + kk, 40);
      }
      for (int mt = 0; mt < 4; mt++) {
        wmma::fragment<wmma::matrix_a, 16, 16, 16, __nv_bfloat16, wmma::row_major> ah, al;
        wmma::load_matrix_sync(ah, sAh + (wm + mt * 16) * 40 + kk, 40);
        wmma::load_matrix_sync(al, sAl + (wm + mt * 16) * 40 + kk, 40);
        wmma::mma_sync(acc[mt][0], ah, bh[0], acc[mt][0]);
        wmma::mma_sync(acc[mt][1], ah, bh[1], acc[mt][1]);
        wmma::mma_sync(acc[mt][0], ah, bl[0], acc[mt][0]);
        wmma::mma_sync(acc[mt][1], ah, bl[1], acc[mt][1]);
        wmma::mma_sync(acc[mt][0], al, bh[0], acc[mt][0]);
        wmma::mma_sync(acc[mt][1], al, bh[1], acc[mt][1]);
      }
    }
    __syncthreads();
    if (kc + 2 < 4) {
      int kn = (kc + 2) * 32;
      for (int i = t; i < 2048; i += 256) {
        int a = i >> 9, idx = i & 511;
        int r = idx >> 2, c = (idx & 3) * 8;
        const __nv_bfloat16* src =
            (a == 0 ? gA0 : a == 1 ? gA1 : a == 2 ? gB0 : gB1)
            + (size_t)r * 128 + kn + c;
        __pipeline_memcpy_async(sm + (kc & 1) * 20480 + a * 5120 + r * 40 + c, src, 16);
      }
      __pipeline_commit();
    }
  }

  for (int mt = 0; mt < 4; mt++)
    for (int j = 0; j < 2; j++) {
      int cc = bn + wn + j * 16;
      if (cc < 10000) {
        int rr = bm + wm + mt * 16;
        wmma::store_matrix_sync(out + (size_t)rr * 10000 + cc, acc[mt][j],
                                10000, wmma::mem_row_major);
      }
    }
}

__global__ void __launch_bounds__(256) k5()
{
  int w = blockIdx.x * 8 + (threadIdx.x >> 5);
  int ln = threadIdx.x & 31;
  int lab = g_ps[w];
  int r = 0;
  for (int j = 0; j < w; j += 32) {
    int jj = j + ln;
    int lj = jj < w ? g_ps[jj] : -1;
    unsigned m = __ballot_sync(0xffffffffu, lj == lab);
    r += __popc(m);
  }
  if (ln == 0) {
    if (r < 32) g_hit[lab * 32 + r] = w;
    atomicAdd(&g_cnt[lab], 1);
  }
}

__global__ void __launch_bounds__(256) k4(const float* pr, const float* q,
    const float* k, float* op)
{
  int c = (blockIdx.x * 256 + threadIdx.x) >> 5, ln = threadIdx.x & 31;
  if (c >= 10000) return;
  float4 pv = ((const float4*)(pr + (size_t)c * 128))[ln];
  float p0 = pv.x, p1 = pv.y, p2 = pv.z, p3 = pv.w;
  int m = g_cnt[c];
  if (m > 32) m = 32;
  for (int r = 0; r < m; r++) {
    int j = g_hit[c * 32 + r];
    const float* f = j < 1024 ? q + (size_t)j * 128 : k + (size_t)(j - 1024) * 128;
    float4 fv = ((const float4*)f)[ln];
    p0 = p0 * 0.99f + 0.01f * fv.x;
    p1 = p1 * 0.99f + 0.01f * fv.y;
    p2 = p2 * 0.99f + 0.01f * fv.z;
    p3 = p3 * 0.99f + 0.01f * fv.w;
  }
  float ss = p0 * p0 + p1 * p1 + p2 * p2 + p3 * p3;
  for (int o = 16; o > 0; o >>= 1) ss += __shfl_xor_sync(0xffffffffu, ss, o);
  float dn = fmaxf(sqrtf(ss), 1e-12f);
  float4 w = make_float4(p0 / dn, p1 / dn, p2 / dn, p3 / dn);
  ((float4*)(op + (size_t)c * 128))[ln] = w;
}

extern "C" void kernel_launch(void* const* d_in, const int* in_sizes, int n_in,
                              void* d_out, int out_size)
{
  const float* oq = (const float*)d_in[0];
  const float* ok = (const float*)d_in[1];
  const float* q  = (const float*)d_in[2];
  const float* k  = (const float*)d_in[3];
  const float* qm = (const float*)d_in[4];
  const float* km = (const float*)d_in[5];
  const float* pY = (const float*)d_in[6];
  const float* P  = (const float*)d_in[7];
  float* out = (float*)d_out;
  cudaFuncSetAttribute(k3, cudaFuncAttributeMaxDynamicSharedMemorySize, 81920);
  k2<<<1776, 256>>>(q, k, qm, km, P);
  k1<<<1024, 256>>>(oq, ok, pY, q, out);
  k3<<<dim3(79, 32), 256, 81920>>>(out + 20480000ull, oq, ok, out);
  k5<<<256, 256>>>();
  k4<<<1250, 256>>>(P, q, k, out + 61571072ull);
}

// round 14
// speedup vs baseline: 1.1511x; 1.1511x over previous
#include <cuda_runtime.h>
#include <cuda_bf16.h>
#include <cuda_pipeline.h>
#include <mma.h>
#include <math.h>

using namespace nvcuda;

__device__ int g_ps[2048];
__device__ int g_cnt[10000];
__device__ int g_hit[320000];
__device__ __nv_bfloat16 g_Ah[524288];
__device__ __nv_bfloat16 g_Al[524288];
__device__ __nv_bfloat16 g_Ph[1294336];
__device__ __nv_bfloat16 g_Pl[1294336];

__device__ __forceinline__ void sp4(float4 v, __nv_bfloat162* dh, __nv_bfloat162* dl)
{
  __nv_bfloat16 h0 = __float2bfloat16_rn(v.x), h1 = __float2bfloat16_rn(v.y);
  __nv_bfloat16 h2 = __float2bfloat16_rn(v.z), h3 = __float2bfloat16_rn(v.w);
  __nv_bfloat16 l0 = __float2bfloat16_rn(v.x - __bfloat162float(h0));
  __nv_bfloat16 l1 = __float2bfloat16_rn(v.y - __bfloat162float(h1));
  __nv_bfloat16 l2 = __float2bfloat16_rn(v.z - __bfloat162float(h2));
  __nv_bfloat16 l3 = __float2bfloat16_rn(v.w - __bfloat162float(h3));
  dh[0] = __halves2bfloat162(h0, h1);
  dh[1] = __halves2bfloat162(h2, h3);
  dl[0] = __halves2bfloat162(l0, l1);
  dl[1] = __halves2bfloat162(l2, l3);
}

__global__ void __launch_bounds__(256) k2(const float* q, const float* k,
    const float* qm, const float* km, const float* P)
{
  int i = blockIdx.x * 256 + threadIdx.x;
  if (i < 10000) g_cnt[i] = 0;
  if (i < 131072) {
    int s = i >> 15;
    const float4* sp = s == 0 ? (const float4*)q : s == 1 ? (const float4*)k :
                       s == 2 ? (const float4*)qm : (const float4*)km;
    sp4(sp[i & 32767], (__nv_bfloat162*)g_Ah + (size_t)i * 2,
        (__nv_bfloat162*)g_Al + (size_t)i * 2);
  } else if (i < 451072) {
    int e = i - 131072;
    sp4(((const float4*)P)[e], (__nv_bfloat162*)g_Ph + (size_t)e * 2,
        (__nv_bfloat162*)g_Pl + (size_t)e * 2);
  } else if (i < 454656) {
    int e = i - 131072;
    sp4(make_float4(0.f, 0.f, 0.f, 0.f), (__nv_bfloat162*)g_Ph + (size_t)e * 2,
        (__nv_bfloat162*)g_Pl + (size_t)e * 2);
  }
}

__global__ void __launch_bounds__(256) k3(float* out, const float* oq,
    const float* ok, const float* pY, const float* q, float* outbase)
{
  extern __shared__ __nv_bfloat16 sm[];
  __shared__ float sv[256];
  __shared__ int si[256];
  int t = threadIdx.x;
  int bn = blockIdx.x * 128, bm = blockIdx.y * 128;
  int wid = t >> 5;
  int wm = (wid >> 2) * 64;
  int wn = (wid & 3) * 32;

  const __nv_bfloat16* gA0 = g_Ah + (size_t)bm * 128;
  const __nv_bfloat16* gA1 = g_Al + (size_t)bm * 128;
  const __nv_bfloat16* gB0 = g_Ph + (size_t)bn * 128;
  const __nv_bfloat16* gB1 = g_Pl + (size_t)bn * 128;

  for (int st = 0; st < 2; st++) {
    int kc = st * 32;
    for (int i = t; i < 2048; i += 256) {
      int a = i >> 9, idx = i & 511;
      int r = idx >> 2, c = (idx & 3) * 8;
      const __nv_bfloat16* src =
          (a == 0 ? gA0 : a == 1 ? gA1 : a == 2 ? gB0 : gB1)
          + (size_t)r * 128 + kc + c;
      __pipeline_memcpy_async(sm + st * 20480 + a * 5120 + r * 40 + c, src, 16);
    }
    __pipeline_commit();
  }

  // ---- fused row job (argmax + pass-through copies) for first 1024 blocks;
  // runs while both cp.async stages stream in. Same traffic as standalone k1.
  int bid = blockIdx.y * 79 + blockIdx.x;
  if (bid < 1024) {
    int row = bid;
    const float4* a4 = (const float4*)(oq + (size_t)row * 10000);
    const float4* b4 = (const float4*)(ok + (size_t)row * 10000);
    const float4* y4 = (const float4*)(pY + (size_t)row * 10000);
    float4* o0 = (float4*)(outbase + (size_t)row * 10000);
    float4* o1 = (float4*)(outbase + 10240000ull + (size_t)row * 10000);
    float bq = -INFINITY, bk = -INFINITY;
    int iq = 0, ik = 0;
    for (int i = t; i < 2500; i += 256) {
      float4 y = y4[i], a = a4[i], b = b4[i];
      o0[i] = a;
      o1[i] = b;
      float w0 = y.x != 0.f ? 1.f : 0.1f;
      float w1 = y.y != 0.f ? 1.f : 0.1f;
      float w2 = y.z != 0.f ? 1.f : 0.1f;
      float w3 = y.w != 0.f ? 1.f : 0.1f;
      float va0 = a.x * w0, va1 = a.y * w1, va2 = a.z * w2, va3 = a.w * w3;
      float vb0 = b.x * w0, vb1 = b.y * w1, vb2 = b.z * w2, vb3 = b.w * w3;
      if (va0 > bq) { bq = va0; iq = i * 4; }
      if (va1 > bq) { bq = va1; iq = i * 4 + 1; }
      if (va2 > bq) { bq = va2; iq = i * 4 + 2; }
      if (va3 > bq) { bq = va3; iq = i * 4 + 3; }
      if (vb0 > bk) { bk = vb0; ik = i * 4; }
      if (vb1 > bk) { bk = vb1; ik = i * 4 + 1; }
      if (vb2 > bk) { bk = vb2; ik = i * 4 + 2; }
      if (vb3 > bk) { bk = vb3; ik = i * 4 + 3; }
    }
    if (t < 32) {
      const float4* q4 = (const float4*)(q + (size_t)row * 128);
      float4* oc = (float4*)(outbase + 61440000ull + (size_t)row * 128);
      oc[t] = q4[t];
    }
    sv[t] = bq; si[t] = iq;
    __syncthreads();
    for (int s = 128; s > 0; s >>= 1) {
      if (t < s) {
        float v = sv[t + s]; int j = si[t + s];
        if (v > sv[t] || (v == sv[t] && j < si[t])) { sv[t] = v; si[t] = j; }
      }
      __syncthreads();
    }
    if (t == 0) g_ps[row] = si[0];
    __syncthreads();
    sv[t] = bk; si[t] = ik;
    __syncthreads();
    for (int s = 128; s > 0; s >>= 1) {
      if (t < s) {
        float v = sv[t + s]; int j = si[t + s];
        if (v > sv[t] || (v == sv[t] && j < si[t])) { sv[t] = v; si[t] = j; }
      }
      __syncthreads();
    }
    if (t == 0) g_ps[1024 + row] = si[0];
  }

  wmma::fragment<wmma::accumulator, 16, 16, 16, float> acc[4][2];
  for (int i = 0; i < 4; i++)
    for (int j = 0; j < 2; j++)
      wmma::fill_fragment(acc[i][j], 0.0f);

  for (int kc = 0; kc < 4; kc++) {
    if (kc >= 2) __pipeline_wait_prior(0);
    else __pipeline_wait_prior(1);
    __syncthreads();
    __nv_bfloat16* sAh = sm + (kc & 1) * 20480;
    __nv_bfloat16* sAl = sAh + 5120;
    __nv_bfloat16* sBh = sAh + 10240;
    __nv_bfloat16* sBl = sAh + 15360;
    for (int kk = 0; kk < 32; kk += 16) {
      wmma::fragment<wmma::matrix_b, 16, 16, 16, __nv_bfloat16, wmma::col_major> bh[2], bl[2];
      for (int j = 0; j < 2; j++) {
        wmma::load_matrix_sync(bh[j], sBh + (wn + j * 16) * 40 + kk, 40);
        wmma::load_matrix_sync(bl[j], sBl + (wn + j * 16) * 40 + kk, 40);
      }
      for (int mt = 0; mt < 4; mt++) {
        wmma::fragment<wmma::matrix_a, 16, 16, 16, __nv_bfloat16, wmma::row_major> ah, al;
        wmma::load_matrix_sync(ah, sAh + (wm + mt * 16) * 40 + kk, 40);
        wmma::load_matrix_sync(al, sAl + (wm + mt * 16) * 40 + kk, 40);
        wmma::mma_sync(acc[mt][0], ah, bh[0], acc[mt][0]);
        wmma::mma_sync(acc[mt][1], ah, bh[1], acc[mt][1]);
        wmma::mma_sync(acc[mt][0], ah, bl[0], acc[mt][0]);
        wmma::mma_sync(acc[mt][1], ah, bl[1], acc[mt][1]);
        wmma::mma_sync(acc[mt][0], al, bh[0], acc[mt][0]);
        wmma::mma_sync(acc[mt][1], al, bh[1], acc[mt][1]);
      }
    }
    __syncthreads();
    if (kc + 2 < 4) {
      int kn = (kc + 2) * 32;
      for (int i = t; i < 2048; i += 256) {
        int a = i >> 9, idx = i & 511;
        int r = idx >> 2, c = (idx & 3) * 8;
        const __nv_bfloat16* src =
            (a == 0 ? gA0 : a == 1 ? gA1 : a == 2 ? gB0 : gB1)
            + (size_t)r * 128 + kn + c;
        __pipeline_memcpy_async(sm + (kc & 1) * 20480 + a * 5120 + r * 40 + c, src, 16);
      }
      __pipeline_commit();
    }
  }

  for (int mt = 0; mt < 4; mt++)
    for (int j = 0; j < 2; j++) {
      int cc = bn + wn + j * 16;
      if (cc < 10000) {
        int rr = bm + wm + mt * 16;
        wmma::store_matrix_sync(out + (size_t)rr * 10000 + cc, acc[mt][j],
                                10000, wmma::mem_row_major);
      }
    }
}

__global__ void __launch_bounds__(256) k5()
{
  int w = blockIdx.x * 8 + (threadIdx.x >> 5);
  int ln = threadIdx.x & 31;
  int lab = g_ps[w];
  int r = 0;
  for (int j = 0; j < w; j += 128) {
    int j0 = j + ln, j1 = j + 32 + ln, j2 = j + 64 + ln, j3 = j + 96 + ln;
    int l0 = j0 < w ? g_ps[j0] : -1;
    int l1 = j1 < w ? g_ps[j1] : -1;
    int l2 = j2 < w ? g_ps[j2] : -1;
    int l3 = j3 < w ? g_ps[j3] : -1;
    r += __popc(__ballot_sync(0xffffffffu, l0 == lab));
    r += __popc(__ballot_sync(0xffffffffu, l1 == lab));
    r += __popc(__ballot_sync(0xffffffffu, l2 == lab));
    r += __popc(__ballot_sync(0xffffffffu, l3 == lab));
  }
  if (ln == 0) {
    if (r < 32) g_hit[lab * 32 + r] = w;
    atomicAdd(&g_cnt[lab], 1);
  }
}

__global__ void __launch_bounds__(256) k4(const float* pr, const float* q,
    const float* k, float* op)
{
  int c = (blockIdx.x * 256 + threadIdx.x) >> 5, ln = threadIdx.x & 31;
  if (c >= 10000) return;
  float4 pv = ((const float4*)(pr + (size_t)c * 128))[ln];
  float p0 = pv.x, p1 = pv.y, p2 = pv.z, p3 = pv.w;
  int m = g_cnt[c];
  if (m > 32) m = 32;
  for (int r = 0; r < m; r++) {
    int j = g_hit[c * 32 + r];
    const float* f = j < 1024 ? q + (size_t)j * 128 : k + (size_t)(j - 1024) * 128;
    float4 fv = ((const float4*)f)[ln];
    p0 = p0 * 0.99f + 0.01f * fv.x;
    p1 = p1 * 0.99f + 0.01f * fv.y;
    p2 = p2 * 0.99f + 0.01f * fv.z;
    p3 = p3 * 0.99f + 0.01f * fv.w;
  }
  float ss = p0 * p0 + p1 * p1 + p2 * p2 + p3 * p3;
  for (int o = 16; o > 0; o >>= 1) ss += __shfl_xor_sync(0xffffffffu, ss, o);
  float dn = fmaxf(sqrtf(ss), 1e-12f);
  float4 w = make_float4(p0 / dn, p1 / dn, p2 / dn, p3 / dn);
  ((float4*)(op + (size_t)c * 128))[ln] = w;
}

extern "C" void kernel_launch(void* const* d_in, const int* in_sizes, int n_in,
                              void* d_out, int out_size)
{
  const float* oq = (const float*)d_in[0];
  const float* ok = (const float*)d_in[1];
  const float* q  = (const float*)d_in[2];
  const float* k  = (const float*)d_in[3];
  const float* qm = (const float*)d_in[4];
  const float* km = (const float*)d_in[5];
  const float* pY = (const float*)d_in[6];
  const float* P  = (const float*)d_in[7];
  float* out = (float*)d_out;
  cudaFuncSetAttribute(k3, cudaFuncAttributeMaxDynamicSharedMemorySize, 81920);
  k2<<<1776, 256>>>(q, k, qm, km, P);
  k3<<<dim3(79, 32), 256, 81920>>>(out + 20480000ull, oq, ok, pY, q, out);
  k5<<<256, 256>>>();
  k4<<<1250, 256>>>(P, q, k, out + 61571072ull);
}

// round 15
// speedup vs baseline: 1.2132x; 1.0539x over previous
#include <cuda_runtime.h>
#include <cuda_bf16.h>
#include <cuda_pipeline.h>
#include <mma.h>
#include <math.h>

using namespace nvcuda;

__device__ int g_ps[2048];
__device__ int g_cnt[10000];
__device__ int g_hit[320000];
__device__ __nv_bfloat16 g_Ah[524288];
__device__ __nv_bfloat16 g_Al[524288];
__device__ __nv_bfloat16 g_Ph[1294336];
__device__ __nv_bfloat16 g_Pl[1294336];

__device__ __forceinline__ void sp4(float4 v, __nv_bfloat162* dh, __nv_bfloat162* dl)
{
  __nv_bfloat16 h0 = __float2bfloat16_rn(v.x), h1 = __float2bfloat16_rn(v.y);
  __nv_bfloat16 h2 = __float2bfloat16_rn(v.z), h3 = __float2bfloat16_rn(v.w);
  __nv_bfloat16 l0 = __float2bfloat16_rn(v.x - __bfloat162float(h0));
  __nv_bfloat16 l1 = __float2bfloat16_rn(v.y - __bfloat162float(h1));
  __nv_bfloat16 l2 = __float2bfloat16_rn(v.z - __bfloat162float(h2));
  __nv_bfloat16 l3 = __float2bfloat16_rn(v.w - __bfloat162float(h3));
  dh[0] = __halves2bfloat162(h0, h1);
  dh[1] = __halves2bfloat162(h2, h3);
  dl[0] = __halves2bfloat162(l0, l1);
  dl[1] = __halves2bfloat162(l2, l3);
}

__global__ void __launch_bounds__(256) k2(const float* q, const float* k,
    const float* qm, const float* km, const float* P)
{
  int i = blockIdx.x * 256 + threadIdx.x;
  if (i < 10000) g_cnt[i] = 0;
  if (i < 131072) {
    int s = i >> 15;
    const float4* sp = s == 0 ? (const float4*)q : s == 1 ? (const float4*)k :
                       s == 2 ? (const float4*)qm : (const float4*)km;
    sp4(sp[i & 32767], (__nv_bfloat162*)g_Ah + (size_t)i * 2,
        (__nv_bfloat162*)g_Al + (size_t)i * 2);
  } else if (i < 451072) {
    int e = i - 131072;
    sp4(((const float4*)P)[e], (__nv_bfloat162*)g_Ph + (size_t)e * 2,
        (__nv_bfloat162*)g_Pl + (size_t)e * 2);
  } else if (i < 454656) {
    int e = i - 131072;
    sp4(make_float4(0.f, 0.f, 0.f, 0.f), (__nv_bfloat162*)g_Ph + (size_t)e * 2,
        (__nv_bfloat162*)g_Pl + (size_t)e * 2);
  }
}

__global__ void __launch_bounds__(256) k3(float* out, const float* oq,
    const float* ok, const float* pY, const float* q, float* outbase)
{
  extern __shared__ __nv_bfloat16 sm[];
  int t = threadIdx.x;
  int bid = blockIdx.x;

  if ((bid & 3) == 3) {
    // ---- dedicated row block: argmax + pass-through copies for one row ----
    __shared__ float sv[256];
    __shared__ int si[256];
    int row = bid >> 2;
    const float4* a4 = (const float4*)(oq + (size_t)row * 10000);
    const float4* b4 = (const float4*)(ok + (size_t)row * 10000);
    const float4* y4 = (const float4*)(pY + (size_t)row * 10000);
    float4* o0 = (float4*)(outbase + (size_t)row * 10000);
    float4* o1 = (float4*)(outbase + 10240000ull + (size_t)row * 10000);
    float bq = -INFINITY, bk = -INFINITY;
    int iq = 0, ik = 0;
    for (int i = t; i < 2500; i += 256) {
      float4 y = y4[i], a = a4[i], b = b4[i];
      o0[i] = a;
      o1[i] = b;
      float w0 = y.x != 0.f ? 1.f : 0.1f;
      float w1 = y.y != 0.f ? 1.f : 0.1f;
      float w2 = y.z != 0.f ? 1.f : 0.1f;
      float w3 = y.w != 0.f ? 1.f : 0.1f;
      float va0 = a.x * w0, va1 = a.y * w1, va2 = a.z * w2, va3 = a.w * w3;
      float vb0 = b.x * w0, vb1 = b.y * w1, vb2 = b.z * w2, vb3 = b.w * w3;
      if (va0 > bq) { bq = va0; iq = i * 4; }
      if (va1 > bq) { bq = va1; iq = i * 4 + 1; }
      if (va2 > bq) { bq = va2; iq = i * 4 + 2; }
      if (va3 > bq) { bq = va3; iq = i * 4 + 3; }
      if (vb0 > bk) { bk = vb0; ik = i * 4; }
      if (vb1 > bk) { bk = vb1; ik = i * 4 + 1; }
      if (vb2 > bk) { bk = vb2; ik = i * 4 + 2; }
      if (vb3 > bk) { bk = vb3; ik = i * 4 + 3; }
    }
    if (t < 32) {
      const float4* q4 = (const float4*)(q + (size_t)row * 128);
      float4* oc = (float4*)(outbase + 61440000ull + (size_t)row * 128);
      oc[t] = q4[t];
    }
    sv[t] = bq; si[t] = iq;
    __syncthreads();
    for (int s = 128; s > 0; s >>= 1) {
      if (t < s) {
        float v = sv[t + s]; int j = si[t + s];
        if (v > sv[t] || (v == sv[t] && j < si[t])) { sv[t] = v; si[t] = j; }
      }
      __syncthreads();
    }
    if (t == 0) g_ps[row] = si[0];
    __syncthreads();
    sv[t] = bk; si[t] = ik;
    __syncthreads();
    for (int s = 128; s > 0; s >>= 1) {
      if (t < s) {
        float v = sv[t + s]; int j = si[t + s];
        if (v > sv[t] || (v == sv[t] && j < si[t])) { sv[t] = v; si[t] = j; }
      }
      __syncthreads();
    }
    if (t == 0) g_ps[1024 + row] = si[0];
    return;
  }

  // ---- GEMM block ----
  int gid = (bid >> 2) * 3 + (bid & 3);
  if (gid >= 2528) return;
  int bn = (gid % 79) * 128, bm = (gid / 79) * 128;
  int wid = t >> 5;
  int wm = (wid >> 2) * 64;
  int wn = (wid & 3) * 32;

  const __nv_bfloat16* gA0 = g_Ah + (size_t)bm * 128;
  const __nv_bfloat16* gA1 = g_Al + (size_t)bm * 128;
  const __nv_bfloat16* gB0 = g_Ph + (size_t)bn * 128;
  const __nv_bfloat16* gB1 = g_Pl + (size_t)bn * 128;

  for (int st = 0; st < 2; st++) {
    int kc = st * 32;
    for (int i = t; i < 2048; i += 256) {
      int a = i >> 9, idx = i & 511;
      int r = idx >> 2, c = (idx & 3) * 8;
      const __nv_bfloat16* src =
          (a == 0 ? gA0 : a == 1 ? gA1 : a == 2 ? gB0 : gB1)
          + (size_t)r * 128 + kc + c;
      __pipeline_memcpy_async(sm + st * 20480 + a * 5120 + r * 40 + c, src, 16);
    }
    __pipeline_commit();
  }

  wmma::fragment<wmma::accumulator, 16, 16, 16, float> acc[4][2];
  for (int i = 0; i < 4; i++)
    for (int j = 0; j < 2; j++)
      wmma::fill_fragment(acc[i][j], 0.0f);

  for (int kc = 0; kc < 4; kc++) {
    if (kc >= 2) __pipeline_wait_prior(0);
    else __pipeline_wait_prior(1);
    __syncthreads();
    __nv_bfloat16* sAh = sm + (kc & 1) * 20480;
    __nv_bfloat16* sAl = sAh + 5120;
    __nv_bfloat16* sBh = sAh + 10240;
    __nv_bfloat16* sBl = sAh + 15360;
    for (int kk = 0; kk < 32; kk += 16) {
      wmma::fragment<wmma::matrix_b, 16, 16, 16, __nv_bfloat16, wmma::col_major> bh[2], bl[2];
      for (int j = 0; j < 2; j++) {
        wmma::load_matrix_sync(bh[j], sBh + (wn + j * 16) * 40 + kk, 40);
        wmma::load_matrix_sync(bl[j], sBl + (wn + j * 16) * 40 + kk, 40);
      }
      for (int mt = 0; mt < 4; mt++) {
        wmma::fragment<wmma::matrix_a, 16, 16, 16, __nv_bfloat16, wmma::row_major> ah, al;
        wmma::load_matrix_sync(ah, sAh + (wm + mt * 16) * 40 + kk, 40);
        wmma::load_matrix_sync(al, sAl + (wm + mt * 16) * 40 + kk, 40);
        wmma::mma_sync(acc[mt][0], ah, bh[0], acc[mt][0]);
        wmma::mma_sync(acc[mt][1], ah, bh[1], acc[mt][1]);
        wmma::mma_sync(acc[mt][0], ah, bl[0], acc[mt][0]);
        wmma::mma_sync(acc[mt][1], ah, bl[1], acc[mt][1]);
        wmma::mma_sync(acc[mt][0], al, bh[0], acc[mt][0]);
        wmma::mma_sync(acc[mt][1], al, bh[1], acc[mt][1]);
      }
    }
    __syncthreads();
    if (kc + 2 < 4) {
      int kn = (kc + 2) * 32;
      for (int i = t; i < 2048; i += 256) {
        int a = i >> 9, idx = i & 511;
        int r = idx >> 2, c = (idx & 3) * 8;
        const __nv_bfloat16* src =
            (a == 0 ? gA0 : a == 1 ? gA1 : a == 2 ? gB0 : gB1)
            + (size_t)r * 128 + kn + c;
        __pipeline_memcpy_async(sm + (kc & 1) * 20480 + a * 5120 + r * 40 + c, src, 16);
      }
      __pipeline_commit();
    }
  }

  for (int mt = 0; mt < 4; mt++)
    for (int j = 0; j < 2; j++) {
      int cc = bn + wn + j * 16;
      if (cc < 10000) {
        int rr = bm + wm + mt * 16;
        wmma::store_matrix_sync(out + (size_t)rr * 10000 + cc, acc[mt][j],
                                10000, wmma::mem_row_major);
      }
    }
}

__global__ void __launch_bounds__(256) k5()
{
  int w = blockIdx.x * 8 + (threadIdx.x >> 5);
  int ln = threadIdx.x & 31;
  int lab = g_ps[w];
  int r = 0;
  for (int j = 0; j < w; j += 128) {
    int j0 = j + ln, j1 = j + 32 + ln, j2 = j + 64 + ln, j3 = j + 96 + ln;
    int l0 = j0 < w ? g_ps[j0] : -1;
    int l1 = j1 < w ? g_ps[j1] : -1;
    int l2 = j2 < w ? g_ps[j2] : -1;
    int l3 = j3 < w ? g_ps[j3] : -1;
    r += __popc(__ballot_sync(0xffffffffu, l0 == lab));
    r += __popc(__ballot_sync(0xffffffffu, l1 == lab));
    r += __popc(__ballot_sync(0xffffffffu, l2 == lab));
    r += __popc(__ballot_sync(0xffffffffu, l3 == lab));
  }
  if (ln == 0) {
    if (r < 32) g_hit[lab * 32 + r] = w;
    atomicAdd(&g_cnt[lab], 1);
  }
}

__global__ void __launch_bounds__(256) k4(const float* pr, const float* q,
    const float* k, float* op)
{
  int c = (blockIdx.x * 256 + threadIdx.x) >> 5, ln = threadIdx.x & 31;
  if (c >= 10000) return;
  float4 pv = ((const float4*)(pr + (size_t)c * 128))[ln];
  float p0 = pv.x, p1 = pv.y, p2 = pv.z, p3 = pv.w;
  int m = g_cnt[c];
  if (m > 32) m = 32;
  for (int r = 0; r < m; r++) {
    int j = g_hit[c * 32 + r];
    const float* f = j < 1024 ? q + (size_t)j * 128 : k + (size_t)(j - 1024) * 128;
    float4 fv = ((const float4*)f)[ln];
    p0 = p0 * 0.99f + 0.01f * fv.x;
    p1 = p1 * 0.99f + 0.01f * fv.y;
    p2 = p2 * 0.99f + 0.01f * fv.z;
    p3 = p3 * 0.99f + 0.01f * fv.w;
  }
  float ss = p0 * p0 + p1 * p1 + p2 * p2 + p3 * p3;
  for (int o = 16; o > 0; o >>= 1) ss += __shfl_xor_sync(0xffffffffu, ss, o);
  float dn = fmaxf(sqrtf(ss), 1e-12f);
  float4 w = make_float4(p0 / dn, p1 / dn, p2 / dn, p3 / dn);
  ((float4*)(op + (size_t)c * 128))[ln] = w;
}

extern "C" void kernel_launch(void* const* d_in, const int* in_sizes, int n_in,
                              void* d_out, int out_size)
{
  const float* oq = (const float*)d_in[0];
  const float* ok = (const float*)d_in[1];
  const float* q  = (const float*)d_in[2];
  const float* k  = (const float*)d_in[3];
  const float* qm = (const float*)d_in[4];
  const float* km = (const float*)d_in[5];
  const float* pY = (const float*)d_in[6];
  const float* P  = (const float*)d_in[7];
  float* out = (float*)d_out;
  cudaFuncSetAttribute(k3, cudaFuncAttributeMaxDynamicSharedMemorySize, 81920);
  k2<<<1776, 256>>>(q, k, qm, km, P);
  k3<<<4096, 256, 81920>>>(out + 20480000ull, oq, ok, pY, q, out);
  k5<<<256, 256>>>();
  k4<<<1250, 256>>>(P, q, k, out + 61571072ull);
}